// round 17
// baseline (speedup 1.0000x reference)
#include <cuda_runtime.h>
#include <cstdint>
#include <cstddef>

#define BB 64
#define SS 2048
#define DIN 512
#define HH 1024
#define SPLITS 8                       // tiles per batch; 512 tiles total
#define NTILES (BB * SPLITS)
#define ROWS_PER_TILE (SS / SPLITS)    // 256
#define NWARP 16
#define RING_DEPTH 3
#define PASS1_GRID 136                 // leave >=16 SMs free for the PDL GEMM
#define GEMM_JOBS 256                  // 8 batch-groups x 32 h-chunks (full K)
#define WT_PITCH 516

#define NEG_INF __int_as_float(0xff800000)

// ---------------- scratch (no allocations allowed) ----------------
__device__ __align__(16) float g_x[BB * HH];            // inp@W + b (by gemm jobs)
__device__ float          g_score[BB * SS];             // raw scores (-inf masked)
__device__ __align__(16) float g_acc[NTILES * HH];      // tile partial weighted sums
__device__ float          g_l[NTILES];                  // tile partial sum-of-exp
__device__ unsigned       g_ticket;                     // tile work queue
__device__ unsigned       g_jdone[8];                   // per-bg gemm-job completion
__device__ unsigned       g_bready[8];                  // per-bg x readiness flag
__device__ unsigned       g_bdone[BB];                  // per-batch tile completion
__device__ unsigned       g_exit;                       // exit counter (for resets)

// ---------------- helpers ----------------
__device__ __forceinline__ float tanh_fast(float x) {
    float y;
    asm("tanh.approx.f32 %0, %1;" : "=f"(y) : "f"(x));
    return y;
}

__device__ __forceinline__ void issue_row(const float* cb, int k, int n,
                                          unsigned slot_u32, int ln,
                                          const int* s_idx) {
    if (k < n) {
        const float* src = cb + (size_t)s_idx[k] * HH + ln * 4;
        unsigned dst = slot_u32 + ln * 16;
#pragma unroll
        for (int i = 0; i < 8; i++)
            asm volatile("cp.async.cg.shared.global [%0], [%1], 16;"
                         :: "r"(dst + i * 512), "l"(src + i * 128) : "memory");
    }
    asm volatile("cp.async.commit_group;" ::: "memory");
}

// ---------------- gemm kernel (PDL secondary; runs on vacant SMs) -----------
// Job = 8 batches x 32 H-cols, full K=512, bias folded. Deterministic.
__global__ __launch_bounds__(256) void gemm_kernel(const float* __restrict__ inp,
                                                   const float* __restrict__ Wm,
                                                   const float* __restrict__ bias) {
    extern __shared__ float gs[];
    float* Wt = gs;                    // [32][WT_PITCH] transposed W slab
    float* Is = gs + 32 * WT_PITCH;    // [8][512] inp rows

    int t  = threadIdx.x;
    int bg = blockIdx.x >> 5;
    int hc = blockIdx.x & 31;
    int b0 = bg * 8, h0 = hc * 32;

    for (int i = t; i < 4096; i += 256) {            // W slab 64KB, transposed
        int k = i >> 3, c4 = i & 7;
        float4 wv = *(const float4*)&Wm[(size_t)k * HH + h0 + c4 * 4];
        Wt[(c4 * 4 + 0) * WT_PITCH + k] = wv.x;
        Wt[(c4 * 4 + 1) * WT_PITCH + k] = wv.y;
        Wt[(c4 * 4 + 2) * WT_PITCH + k] = wv.z;
        Wt[(c4 * 4 + 3) * WT_PITCH + k] = wv.w;
    }
    for (int i = t; i < 1024; i += 256) {            // inp rows 16KB
        int b = i >> 7, kq = i & 127;
        *(float4*)&Is[b * 512 + kq * 4] =
            *(const float4*)&inp[(b0 + b) * DIN + kq * 4];
    }
    __syncthreads();

    int b = t & 7, h = t >> 3;                       // broadcast-friendly map
    const float4* ip = (const float4*)&Is[b * 512];
    const float4* wp = (const float4*)&Wt[h * WT_PITCH];
    float a0 = 0.f, a1 = 0.f, a2 = 0.f, a3 = 0.f;
#pragma unroll 16
    for (int kq = 0; kq < 128; kq++) {
        float4 iv = ip[kq];
        float4 wv = wp[kq];
        a0 = fmaf(iv.x, wv.x, a0);
        a1 = fmaf(iv.y, wv.y, a1);
        a2 = fmaf(iv.z, wv.z, a2);
        a3 = fmaf(iv.w, wv.w, a3);
    }
    g_x[(size_t)(b0 + b) * HH + h0 + h] = ((a0 + a1) + (a2 + a3)) + bias[h0 + h];

    __syncthreads();                                 // all stores issued
    if (t == 0) {
        __threadfence();
        unsigned old = atomicAdd(&g_jdone[bg], 1u);
        if (old == 31) atomicExch(&g_bready[bg], 1u);  // release batch-group
    }
}

// ---------------- pass1 (PDL primary; persistent champion loop) -------------
__global__ __launch_bounds__(512, 1) void pass1_kernel(const void*  __restrict__ mraw,
                                                       const float* __restrict__ ctx,
                                                       const float* __restrict__ v,
                                                       float* __restrict__ out_applied,
                                                       float* __restrict__ out_w) {
    // release the dependent gemm kernel onto the vacant SMs immediately
    asm volatile("griddepcontrol.launch_dependents;" ::: "memory");

    extern __shared__ float dsm[];
    float* xs   = dsm;                 // HH floats
    float* ring = dsm + HH;            // NWARP * RING_DEPTH * HH floats

    __shared__ int      s_idx[ROWS_PER_TILE];
    __shared__ int      s_wcnt[8];
    __shared__ float    s_l[NWARP];
    __shared__ unsigned s_tile;
    __shared__ int      s_last;

    int t  = threadIdx.x;
    int w  = t >> 5;
    int ln = t & 31;

    // ---- mask encoding detection (once per CTA; first 4KB) ----
    int mode;
    {
        const unsigned* wds = (const unsigned*)mraw;
        int notInt = 0, notFloat = 0;
        for (int i = t; i < 1024; i += 512) {
            unsigned x = wds[i];
            notInt   |= (x > 1u);
            notFloat |= (x != 0u && x != 0x3F800000u);
        }
        notInt   = __syncthreads_or(notInt);
        notFloat = __syncthreads_or(notFloat);
        mode = notInt ? (notFloat ? 2 : 1) : 0;   // 0:int32 1:float32 2:bytes
    }

    float4 vv[8];
    const float4* vr = (const float4*)v;
#pragma unroll
    for (int j = 0; j < 8; j++) vv[j] = __ldg(&vr[j * 32 + ln]);

    float* myring = ring + w * (RING_DEPTH * HH);
    unsigned ring_u32 = (unsigned)__cvta_generic_to_shared(myring);

    for (;;) {
        if (t == 0) s_tile = atomicAdd(&g_ticket, 1u);
        __syncthreads();               // orders prior tile's smem reuse
        unsigned tile = s_tile;
        if (tile >= NTILES) break;

        int b  = tile >> 3;            // SPLITS = 8
        int sp = tile & (SPLITS - 1);
        int rowbase = b * SS + sp * ROWS_PER_TILE;

        // ---- mask from raw + compact unmasked row indices ----
        unsigned char mk = 1;
        if (t < ROWS_PER_TILE) {
            int gi = rowbase + t;
            if (mode == 0)      mk = (((const int*)mraw)[gi] != 0);
            else if (mode == 1) mk = (((const float*)mraw)[gi] != 0.0f);
            else                mk = (((const unsigned char*)mraw)[gi] != 0);
        }
        unsigned bits = __ballot_sync(0xffffffffu, mk == 0);
        if (t < ROWS_PER_TILE && mk) g_score[rowbase + t] = NEG_INF;
        if (w < 8 && ln == 0) s_wcnt[w] = __popc(bits);
        __syncthreads();
        int n = 0;
#pragma unroll
        for (int i = 0; i < 8; i++) n += s_wcnt[i];
        if (t < ROWS_PER_TILE && !mk) {
            int basew = 0;
#pragma unroll
            for (int i = 0; i < 8; i++) if (i < w) basew += s_wcnt[i];
            s_idx[basew + __popc(bits & ((1u << ln) - 1u))] = t;
        }
        __syncthreads();

        // ---- prefetch first rows NOW (independent of x) ----
        const float* cb = ctx + (size_t)rowbase * HH;
        issue_row(cb, w,             n, ring_u32,          ln, s_idx);
        issue_row(cb, w + NWARP,     n, ring_u32 + HH * 4, ln, s_idx);
        issue_row(cb, w + 2 * NWARP, n, ring_u32 + HH * 8, ln, s_idx);

        // ---- wait for this batch-group's x (overlaps with prefetch) ----
        if (t == 0) {
            unsigned r;
            do {
                asm volatile("ld.acquire.gpu.global.b32 %0, [%1];"
                             : "=r"(r) : "l"(&g_bready[b >> 3]) : "memory");
            } while (!r);
        }
        __syncthreads();
        xs[t]       = g_x[b * HH + t];
        xs[t + 512] = g_x[b * HH + 512 + t];
        __syncthreads();

        // ---- per-warp row loop over compacted list (champion loop) ----
        float4 acc[8];
#pragma unroll
        for (int j = 0; j < 8; j++) acc[j] = make_float4(0.f, 0.f, 0.f, 0.f);
        float l = 0.f;

        int slot = 0;
        for (int k = w; k < n; k += NWARP) {
            asm volatile("cp.async.wait_group 2;" ::: "memory");
            const float* sp_ = myring + slot * HH;

            float part = 0.f;
#pragma unroll
            for (int j = 0; j < 8; j++) {
                float4 c  = *(const float4*)&sp_[j * 128 + ln * 4];
                float4 xj = *(const float4*)&xs[j * 128 + ln * 4];
                float4 vg = vv[j];
                part = fmaf(tanh_fast(xj.x + c.x), vg.x, part);
                part = fmaf(tanh_fast(xj.y + c.y), vg.y, part);
                part = fmaf(tanh_fast(xj.z + c.z), vg.z, part);
                part = fmaf(tanh_fast(xj.w + c.w), vg.w, part);
            }
#pragma unroll
            for (int off = 16; off; off >>= 1)
                part += __shfl_xor_sync(0xffffffffu, part, off);

            if (ln == 0) g_score[rowbase + s_idx[k]] = part;
            float p = __expf(part);    // fixed reference M=0: |score| < 40
            l += p;
#pragma unroll
            for (int j = 0; j < 8; j++) {          // re-read row (LDS, no spill)
                float4 c = *(const float4*)&sp_[j * 128 + ln * 4];
                acc[j].x = fmaf(c.x, p, acc[j].x);
                acc[j].y = fmaf(c.y, p, acc[j].y);
                acc[j].z = fmaf(c.z, p, acc[j].z);
                acc[j].w = fmaf(c.w, p, acc[j].w);
            }
            issue_row(cb, k + 3 * NWARP, n, ring_u32 + slot * HH * 4, ln, s_idx);
            slot = (slot == RING_DEPTH - 1) ? 0 : slot + 1;
        }
        asm volatile("cp.async.wait_group 0;" ::: "memory");

        // ---- CTA combine: overlay acc onto ring smem, tree-reduce ----
        if (ln == 0) s_l[w] = l;
        __syncthreads();
        float* sout = ring;
#pragma unroll
        for (int j = 0; j < 8; j++)
            *(float4*)&sout[w * HH + j * 128 + ln * 4] = acc[j];
        __syncthreads();

        float L = 0.f;
#pragma unroll
        for (int i = 0; i < NWARP; i++) L += s_l[i];
        float sum0 = 0.f, sum1 = 0.f;
#pragma unroll
        for (int i = 0; i < NWARP; i++) {
            sum0 += sout[i * HH + t];
            sum1 += sout[i * HH + t + 512];
        }
        g_acc[(size_t)tile * HH + t]       = sum0;
        g_acc[(size_t)tile * HH + t + 512] = sum1;
        if (t == 0) g_l[tile] = L;

        // ---- last tile of this batch? finalize the batch here ----
        __threadfence();
        if (t == 0) {
            unsigned old = atomicAdd(&g_bdone[b], 1u);
            s_last = (old == SPLITS - 1);
        }
        __syncthreads();
        if (s_last) {
            float Lb = 0.f;
#pragma unroll
            for (int i = 0; i < SPLITS; i++) Lb += __ldcg(&g_l[b * SPLITS + i]);
            float invL = 1.0f / Lb;
#pragma unroll
            for (int r = 0; r < 2; r++) {
                int h = t + r * 512;
                float s = 0.f;
#pragma unroll
                for (int i = 0; i < SPLITS; i++)
                    s += __ldcg(&g_acc[(size_t)(b * SPLITS + i) * HH + h]);
                out_applied[b * HH + h] = s * invL;
            }
#pragma unroll
            for (int r = 0; r < 4; r++) {
                int si = t + r * 512;
                float sc = __ldcg(&g_score[b * SS + si]);  // -inf masked -> 0
                out_w[b * SS + si] = __expf(sc) * invL;
            }
        }
    }

    // ---- exit: last CTA resets all persistent state for graph replay ----
    // (safe: pass1 drains only after every g_bready is set => gemm finished)
    __syncthreads();
    if (t == 0) {
        __threadfence();
        unsigned old = atomicAdd(&g_exit, 1u);
        if (old == PASS1_GRID - 1) {
            g_ticket = 0;
#pragma unroll
            for (int i = 0; i < 8; i++) { g_jdone[i] = 0; g_bready[i] = 0; }
#pragma unroll
            for (int i = 0; i < BB; i++) g_bdone[i] = 0;
            g_exit = 0;
        }
    }
}

// ---------------- launch ----------------
extern "C" void kernel_launch(void* const* d_in, const int* in_sizes, int n_in,
                              void* d_out, int out_size) {
    const float* inp  = (const float*)d_in[0];
    // d_in[1] = hidden (unused by the reference computation)
    const float* ctx  = (const float*)d_in[2];
    const void*  mask = d_in[3];
    const float* Wm   = (const float*)d_in[4];
    const float* bias = (const float*)d_in[5];
    const float* v    = (const float*)d_in[6];
    float* out = (float*)d_out;

    const int p1_smem   = (HH + NWARP * RING_DEPTH * HH) * (int)sizeof(float); // 200704
    const int gemm_smem = (32 * WT_PITCH + 8 * 512) * (int)sizeof(float);      // 82432
    cudaFuncSetAttribute(pass1_kernel,
                         cudaFuncAttributeMaxDynamicSharedMemorySize, p1_smem);
    cudaFuncSetAttribute(gemm_kernel,
                         cudaFuncAttributeMaxDynamicSharedMemorySize, gemm_smem);

    // primary: persistent attention kernel (owns 136 SMs, triggers dependents)
    pass1_kernel<<<PASS1_GRID, 512, p1_smem>>>(mask, ctx, v,
                                               out, out + BB * HH);

    // secondary: GEMM with programmatic dependent launch -> overlaps primary
    cudaLaunchConfig_t cfg = {};
    cfg.gridDim          = dim3(GEMM_JOBS, 1, 1);
    cfg.blockDim         = dim3(256, 1, 1);
    cfg.dynamicSmemBytes = gemm_smem;
    cfg.stream           = 0;
    cudaLaunchAttribute attrs[1];
    attrs[0].id = cudaLaunchAttributeProgrammaticStreamSerialization;
    attrs[0].val.programmaticStreamSerializationAllowed = 1;
    cfg.attrs    = attrs;
    cfg.numAttrs = 1;
    cudaLaunchKernelEx(&cfg, gemm_kernel, inp, Wm, bias);
}